// round 8
// baseline (speedup 1.0000x reference)
#include <cuda_runtime.h>
#include <cuda_fp16.h>

// LessonGCN on GB300: out = GCNConv(relu(GCNConv(x)))
// (A_norm @ x) @ W1 reordering; layer 2 (OUT_DIM=1) fused into GEMM epilogue.
// R8: fp16 x copy for the edge gather (halves agg_x L2 traffic; fp32 accumulate,
//     fp32 self-loop). Convert fused into the prep kernel. Rest unchanged from R7.

#define N_NODES 100000
#define N_EDGES 1600000
#define IN_DIM  64
#define HID_DIM 128
#define SCAN_B  1024
#define NB_SCAN ((N_NODES + SCAN_B - 1) / SCAN_B)   // 98
#define GM      128                                  // nodes per gemm block
#define GPAD    132                                  // sYt row stride (floats)
#define GEMM_SMEM ((IN_DIM * GPAD + IN_DIM * HID_DIM) * 4)  // 66560 bytes

__device__ int   g_cnt[N_NODES];
__device__ int   g_off[N_NODES];
__device__ int   g_part[NB_SCAN];
__device__ int   g_csr_src[N_EDGES];
__device__ float g_dinv[N_NODES];
__device__ __align__(16) float   g_y[(size_t)N_NODES * IN_DIM];
__device__ __align__(8)  __half2 g_xh[(size_t)N_NODES * (IN_DIM / 2)];
__device__ float g_h2[N_NODES];

// Prep: zero counts + convert x -> fp16 (one half2 per thread).
__global__ void k_prep(const float2* __restrict__ x2) {
    int i = blockIdx.x * blockDim.x + threadIdx.x;
    if (i < N_NODES * (IN_DIM / 2)) {
        float2 v = x2[i];
        g_xh[i] = __floats2half2_rn(v.x, v.y);
    }
    if (i < N_NODES) g_cnt[i] = 0;
}

__global__ void k_count(const int* __restrict__ dst) {
    int e = blockIdx.x * blockDim.x + threadIdx.x;
    if (e >= N_EDGES) return;
    unsigned d = (unsigned)dst[e];
    if (d < N_NODES) atomicAdd(&g_cnt[d], 1);
}

// Block-level exclusive scan of g_cnt -> g_off (block-local), totals -> g_part.
__global__ __launch_bounds__(SCAN_B) void k_scan1() {
    __shared__ int s[SCAN_B];
    int t = threadIdx.x;
    int idx = blockIdx.x * SCAN_B + t;
    int c = (idx < N_NODES) ? g_cnt[idx] : 0;
    s[t] = c;
    __syncthreads();
#pragma unroll
    for (int d = 1; d < SCAN_B; d <<= 1) {
        int v = (t >= d) ? s[t - d] : 0;
        __syncthreads();
        s[t] += v;
        __syncthreads();
    }
    if (idx < N_NODES) g_off[idx] = s[t] - c;
    if (t == SCAN_B - 1) g_part[blockIdx.x] = s[t];
}

// Finalize: every block redundantly scans the 98 partials; adds global offset;
// computes dinv.
__global__ __launch_bounds__(256) void k_scan_fin() {
    __shared__ int sp[128];
    int t = threadIdx.x;
    if (t < 128) {
        int c = (t < NB_SCAN) ? g_part[t] : 0;
        sp[t] = c;
    }
    __syncthreads();
#pragma unroll
    for (int d = 1; d < 128; d <<= 1) {
        int v = 0;
        if (t < 128 && t >= d) v = sp[t - d];
        __syncthreads();
        if (t < 128) sp[t] += v;
        __syncthreads();
    }
    int i = blockIdx.x * blockDim.x + t;
    if (i >= N_NODES) return;
    int blk = i / SCAN_B;
    int excl = (blk == 0) ? 0 : sp[blk - 1];
    g_off[i] += excl;
    g_dinv[i] = rsqrtf((float)g_cnt[i] + 1.0f);
}

// Scatter src ids into CSR; g_off[d] advances to segment end (= off + cnt).
__global__ void k_scatter(const int* __restrict__ src,
                          const int* __restrict__ dst) {
    int e = blockIdx.x * blockDim.x + threadIdx.x;
    if (e >= N_EDGES) return;
    unsigned s = (unsigned)src[e];
    unsigned d = (unsigned)dst[e];
    if (s >= N_NODES || d >= N_NODES) return;
    int p = atomicAdd(&g_off[d], 1);
    g_csr_src[p] = (int)s;
}

// Warp per node. Lanes cooperatively prefetch 32 (src,dinv) pairs, broadcast
// via shfl; gather fp16 x rows (one LDG.32/lane/edge), accumulate fp32.
// Self-loop uses exact fp32 x. Zero atomics.
__global__ __launch_bounds__(256) void k_agg_x(const float2* __restrict__ x2) {
    int w = (blockIdx.x * blockDim.x + threadIdx.x) >> 5;
    int lane = threadIdx.x & 31;
    if (w >= N_NODES) return;
    int n = w;
    int cnt = g_cnt[n];
    int base = g_off[n] - cnt;
    float dn = g_dinv[n];

    float2 acc = make_float2(0.f, 0.f);
    for (int j0 = 0; j0 < cnt; j0 += 32) {
        int rem = cnt - j0;
        int id = 0; float dv = 0.f;
        if (lane < rem) { id = g_csr_src[base + j0 + lane]; dv = g_dinv[id]; }
        int m = rem < 32 ? rem : 32;
        int jj = 0;
        for (; jj + 4 <= m; jj += 4) {
            int s0 = __shfl_sync(0xFFFFFFFFu, id, jj);
            int s1 = __shfl_sync(0xFFFFFFFFu, id, jj + 1);
            int s2 = __shfl_sync(0xFFFFFFFFu, id, jj + 2);
            int s3 = __shfl_sync(0xFFFFFFFFu, id, jj + 3);
            float n0 = __shfl_sync(0xFFFFFFFFu, dv, jj) * dn;
            float n1 = __shfl_sync(0xFFFFFFFFu, dv, jj + 1) * dn;
            float n2 = __shfl_sync(0xFFFFFFFFu, dv, jj + 2) * dn;
            float n3 = __shfl_sync(0xFFFFFFFFu, dv, jj + 3) * dn;
            float2 v0 = __half22float2(g_xh[(size_t)s0 * 32 + lane]);
            float2 v1 = __half22float2(g_xh[(size_t)s1 * 32 + lane]);
            float2 v2 = __half22float2(g_xh[(size_t)s2 * 32 + lane]);
            float2 v3 = __half22float2(g_xh[(size_t)s3 * 32 + lane]);
            acc.x = fmaf(v0.x, n0, acc.x); acc.y = fmaf(v0.y, n0, acc.y);
            acc.x = fmaf(v1.x, n1, acc.x); acc.y = fmaf(v1.y, n1, acc.y);
            acc.x = fmaf(v2.x, n2, acc.x); acc.y = fmaf(v2.y, n2, acc.y);
            acc.x = fmaf(v3.x, n3, acc.x); acc.y = fmaf(v3.y, n3, acc.y);
        }
        for (; jj < m; jj++) {
            int s0 = __shfl_sync(0xFFFFFFFFu, id, jj);
            float n0 = __shfl_sync(0xFFFFFFFFu, dv, jj) * dn;
            float2 v0 = __half22float2(g_xh[(size_t)s0 * 32 + lane]);
            acc.x = fmaf(v0.x, n0, acc.x); acc.y = fmaf(v0.y, n0, acc.y);
        }
    }
    float sl = dn * dn;  // self-loop: exact fp32 x[n] * dinv^2
    float2 vs = x2[(size_t)n * 32 + lane];
    acc.x = fmaf(vs.x, sl, acc.x);
    acc.y = fmaf(vs.y, sl, acc.y);
    reinterpret_cast<float2*>(g_y)[(size_t)n * 32 + lane] = acc;
}

// Register-blocked GEMM + fused epilogue.
// Block: 256 threads = 16 tx (j-slices of 8) x 16 ty (node-slices of 8), 128 nodes.
__global__ __launch_bounds__(256) void k_gemm_fused(
    const float* __restrict__ W1, const float* __restrict__ b1,
    const float* __restrict__ W2, const float* __restrict__ b2,
    float* __restrict__ out) {
    extern __shared__ float smem_dyn[];
    float* sYt = smem_dyn;                    // [IN_DIM][GPAD]
    float* sW1 = smem_dyn + IN_DIM * GPAD;    // [IN_DIM][HID_DIM]

    int t = threadIdx.x;
    int node0 = blockIdx.x * GM;

    {
        const float4* W14 = reinterpret_cast<const float4*>(W1);
        float4* sW14 = reinterpret_cast<float4*>(sW1);
        for (int i = t; i < IN_DIM * HID_DIM / 4; i += 256) sW14[i] = W14[i];
    }
    for (int i = t; i < GM * (IN_DIM / 4); i += 256) {
        int ln = i & (GM - 1);
        int kc = i >> 7;            // 0..15
        int n = node0 + ln;
        float4 v = (n < N_NODES)
                       ? reinterpret_cast<const float4*>(g_y)[(size_t)n * 16 + kc]
                       : make_float4(0.f, 0.f, 0.f, 0.f);
        int k = kc * 4;
        sYt[(k + 0) * GPAD + ln] = v.x;
        sYt[(k + 1) * GPAD + ln] = v.y;
        sYt[(k + 2) * GPAD + ln] = v.z;
        sYt[(k + 3) * GPAD + ln] = v.w;
    }
    __syncthreads();

    int tx = t & 15;
    int ty = t >> 4;
    int jb = tx * 8;
    int nb = ty * 8;

    unsigned long long acc[8][4];
#pragma unroll
    for (int a = 0; a < 8; a++)
#pragma unroll
        for (int p = 0; p < 4; p++) acc[a][p] = 0ull;

#pragma unroll 8
    for (int k = 0; k < IN_DIM; k++) {
        const float4* yp = reinterpret_cast<const float4*>(&sYt[k * GPAD + nb]);
        float4 ya = yp[0], yb = yp[1];
        float yv[8] = {ya.x, ya.y, ya.z, ya.w, yb.x, yb.y, yb.z, yb.w};
        const ulonglong2* wp = reinterpret_cast<const ulonglong2*>(&sW1[k * HID_DIM + jb]);
        ulonglong2 w0 = wp[0], w1 = wp[1];
        unsigned long long wj[4] = {w0.x, w0.y, w1.x, w1.y};
#pragma unroll
        for (int a = 0; a < 8; a++) {
            unsigned long long yd;
            asm("mov.b64 %0, {%1, %1};" : "=l"(yd) : "f"(yv[a]));
#pragma unroll
            for (int p = 0; p < 4; p++)
                asm("fma.rn.f32x2 %0, %1, %2, %0;"
                    : "+l"(acc[a][p]) : "l"(yd), "l"(wj[p]));
        }
    }

    float4 b1a = *reinterpret_cast<const float4*>(b1 + jb);
    float4 b1b = *reinterpret_cast<const float4*>(b1 + jb + 4);
    float4 w2a = *reinterpret_cast<const float4*>(W2 + jb);
    float4 w2b = *reinterpret_cast<const float4*>(W2 + jb + 4);
    float b1r[8] = {b1a.x, b1a.y, b1a.z, b1a.w, b1b.x, b1b.y, b1b.z, b1b.w};
    float w2r[8] = {w2a.x, w2a.y, w2a.z, w2a.w, w2b.x, w2b.y, w2b.z, w2b.w};

    float part[8];
#pragma unroll
    for (int a = 0; a < 8; a++) {
        float s = 0.f;
#pragma unroll
        for (int p = 0; p < 4; p++) {
            float lo, hi;
            asm("mov.b64 {%0, %1}, %2;" : "=f"(lo), "=f"(hi) : "l"(acc[a][p]));
            s = fmaf(fmaxf(lo + b1r[2 * p], 0.f), w2r[2 * p], s);
            s = fmaf(fmaxf(hi + b1r[2 * p + 1], 0.f), w2r[2 * p + 1], s);
        }
        part[a] = s;
    }
#pragma unroll
    for (int m = 1; m < 16; m <<= 1)
#pragma unroll
        for (int a = 0; a < 8; a++)
            part[a] += __shfl_xor_sync(0xFFFFFFFFu, part[a], m);

    if (tx == 0) {
        float bias2 = b2[0];
#pragma unroll
        for (int a = 0; a < 8; a++) {
            int n = node0 + nb + a;
            if (n < N_NODES) {
                float dinv = g_dinv[n];
                g_h2[n] = part[a];
                out[n] = fmaf(part[a], dinv * dinv, bias2);
            }
        }
    }
}

// Warp per node: gather h2[src]*dinv[src], warp-reduce, lane0 accumulates.
__global__ __launch_bounds__(256) void k_agg_h2(float* __restrict__ out) {
    int w = (blockIdx.x * blockDim.x + threadIdx.x) >> 5;
    int lane = threadIdx.x & 31;
    if (w >= N_NODES) return;
    int n = w;
    int cnt = g_cnt[n];
    int base = g_off[n] - cnt;

    float acc = 0.0f;
    for (int j = lane; j < cnt; j += 32) {
        int s = g_csr_src[base + j];
        acc += g_h2[s] * g_dinv[s];
    }
#pragma unroll
    for (int o = 16; o > 0; o >>= 1)
        acc += __shfl_down_sync(0xFFFFFFFFu, acc, o);
    if (lane == 0)
        out[n] += acc * g_dinv[n];
}

extern "C" void kernel_launch(void* const* d_in, const int* in_sizes, int n_in,
                              void* d_out, int out_size) {
    const float* x   = (const float*)d_in[0];
    const int*   ei  = (const int*)d_in[1];   // int32 (JAX x64 disabled)
    const float* W1  = (const float*)d_in[2];
    const float* b1  = (const float*)d_in[3];
    const float* W2  = (const float*)d_in[4];
    const float* b2  = (const float*)d_in[5];
    float* out       = (float*)d_out;

    const int* src = ei;
    const int* dst = ei + N_EDGES;

    cudaFuncSetAttribute(k_gemm_fused,
                         cudaFuncAttributeMaxDynamicSharedMemorySize, GEMM_SMEM);

    const int T = 256;
    k_prep<<<(N_NODES * (IN_DIM / 2) + T - 1) / T, T>>>((const float2*)x);
    k_count<<<(N_EDGES + T - 1) / T, T>>>(dst);
    k_scan1<<<NB_SCAN, SCAN_B>>>();
    k_scan_fin<<<(N_NODES + T - 1) / T, T>>>();
    k_scatter<<<(N_EDGES + T - 1) / T, T>>>(src, dst);
    k_agg_x<<<(N_NODES * 32 + T - 1) / T, T>>>((const float2*)x);
    k_gemm_fused<<<(N_NODES + GM - 1) / GM, 256, GEMM_SMEM>>>(W1, b1, W2, b2, out);
    k_agg_h2<<<(N_NODES * 32 + T - 1) / T, T>>>(out);
}